// round 13
// baseline (speedup 1.0000x reference)
#include <cuda_runtime.h>
#include <cuda_fp16.h>
#include <cstdint>

// ---------------- problem constants ----------------
#define NN 50000          // nodes
#define NE 800000         // edges
#define IND 256
#define HID 128
#define OUTD 64

#define NBLK_SCAN 49      // ceil(50000/1024)

// ---------------- device scratch (no allocation allowed) ----------------
__device__ __align__(128) int    g_degflag[NN + NBLK_SCAN]; // [0,NN)=deg, [NN,..)=scan flags
__device__ __align__(128) float  g_dinv[NN];
__device__ __align__(128) int    g_rowoff[NN + 1];
__device__ __align__(128) int    g_src[NE];
__device__ __align__(128) int    g_dst[NE];
__device__ __align__(128) int    g_rank[NE];
__device__ __align__(128) int    g_col[NE];
__device__ __align__(128) __half g_H1h[(size_t)NN * HID];  // x @ W1, fp16
__device__ __align__(128) __half g_A1h[(size_t)NN * HID];  // relu(agg(H1)+b1), fp16
__device__ __align__(128) __half g_H2h[(size_t)NN * OUTD]; // A1 @ W2, fp16

// fp16 weight images, n-major: img[n][k] (col-major B for mma.row.col)
__device__ __align__(128) __half g_w1h[HID * IND];          // W1 hi only (fp16 GEMM1)
__device__ __align__(128) __half g_w2h[OUTD * HID];
__device__ __align__(128) __half g_w2l[OUTD * HID];

// ---------------- convert + degree count + per-edge rank, 4 edges/thread ----
__global__ void k_convert_count4(const void* __restrict__ edges) {
    const int* e32 = (const int*)edges;
    unsigned bal = __ballot_sync(~0u, e32[(threadIdx.x & 31) * 2 + 1] != 0);
    const bool is64 = (bal == 0);

    int q = blockIdx.x * blockDim.x + threadIdx.x;   // quad index
    if (q >= NE / 4) return;
    int s0, s1, s2, s3, d0, d1, d2, d3;
    if (is64) {
        const longlong2* p = (const longlong2*)edges;
        const longlong2* pd = p + NE / 2;
        longlong2 a = p[q * 2], b = p[q * 2 + 1];
        longlong2 c = pd[q * 2], e = pd[q * 2 + 1];
        s0 = (int)a.x; s1 = (int)a.y; s2 = (int)b.x; s3 = (int)b.y;
        d0 = (int)c.x; d1 = (int)c.y; d2 = (int)e.x; d3 = (int)e.y;
    } else {
        const int4* p = (const int4*)edges;
        const int4* pd = p + NE / 4;
        int4 a = p[q], c = pd[q];
        s0 = a.x; s1 = a.y; s2 = a.z; s3 = a.w;
        d0 = c.x; d1 = c.y; d2 = c.z; d3 = c.w;
    }
    *(int4*)&g_src[q * 4] = make_int4(s0, s1, s2, s3);
    *(int4*)&g_dst[q * 4] = make_int4(d0, d1, d2, d3);
    int r0 = atomicAdd(&g_degflag[d0], 1);
    int r1 = atomicAdd(&g_degflag[d1], 1);
    int r2 = atomicAdd(&g_degflag[d2], 1);
    int r3 = atomicAdd(&g_degflag[d3], 1);
    *(int4*)&g_rank[q * 4] = make_int4(r0, r1, r2, r3);
}

// ---------------- single-kernel scan (decoupled lookback) + dinv ----------------
__global__ void __launch_bounds__(1024) k_scan() {
    __shared__ int wsum[32];
    __shared__ int s_prefix;
    const int tid = threadIdx.x, lane = tid & 31, wid = tid >> 5;
    const int bid = blockIdx.x;
    const int i = bid * 1024 + tid;

    int v = (i < NN) ? g_degflag[i] : 0;
    if (i < NN) g_dinv[i] = rsqrtf((float)(v + 1));

    int incl = v;
    #pragma unroll
    for (int o = 1; o < 32; o <<= 1) {
        int t = __shfl_up_sync(~0u, incl, o);
        if (lane >= o) incl += t;
    }
    if (lane == 31) wsum[wid] = incl;
    if (tid == 0) s_prefix = 0;
    __syncthreads();
    if (wid == 0) {
        int w = wsum[lane];
        #pragma unroll
        for (int o = 1; o < 32; o <<= 1) {
            int t = __shfl_up_sync(~0u, w, o);
            if (lane >= o) w += t;
        }
        wsum[lane] = w;
    }
    __syncthreads();
    if (wid > 0) incl += wsum[wid - 1];
    const int bsum = wsum[31];

    if (tid == 0) atomicExch(&g_degflag[NN + bid], bsum + 1);
    if (tid < bid) {
        int f;
        do { f = atomicAdd(&g_degflag[NN + tid], 0); } while (f == 0);
        atomicAdd_block(&s_prefix, f - 1);
    }
    __syncthreads();
    const int excl = s_prefix + incl - v;
    if (i < NN) g_rowoff[i] = excl;
    if (i == NN - 1) g_rowoff[NN] = excl + v;
}

// CSR fill, atomic-free, 2 edges/thread
__global__ void k_fill2() {
    int q = blockIdx.x * blockDim.x + threadIdx.x;
    if (q >= NE / 2) return;
    int2 s = *(const int2*)&g_src[q * 2];
    int2 d = *(const int2*)&g_dst[q * 2];
    int2 r = *(const int2*)&g_rank[q * 2];
    g_col[__ldg(&g_rowoff[d.x]) + r.x] = s.x;
    g_col[__ldg(&g_rowoff[d.y]) + r.y] = s.y;
}

// ---------------- weight pack (output-coalesced) ----------------
// W1 -> hi only; W2 -> hi + lo
__global__ void k_pack(const float* __restrict__ W1, const float* __restrict__ W2) {
    int i = blockIdx.x * blockDim.x + threadIdx.x;
    if (i < HID * IND) {                 // out index: n*IND + k
        int n = i / IND, k = i % IND;
        g_w1h[i] = __float2half_rn(__ldg(&W1[k * HID + n]));
    }
    if (i < OUTD * HID) {                // out index: n*HID + k
        int n = i / HID, k = i % HID;
        float v = __ldg(&W2[k * OUTD + n]);
        __half h = __float2half_rn(v);
        __half l = __float2half_rn(v - __half2float(h));
        g_w2h[i] = h;
        g_w2l[i] = l;
    }
}

// ---------------- HMMA primitives ----------------
__device__ __forceinline__ void mma16816(float* c, const uint32_t* a,
                                         uint32_t b0, uint32_t b1) {
    asm volatile(
        "mma.sync.aligned.m16n8k16.row.col.f32.f16.f16.f32 "
        "{%0,%1,%2,%3}, {%4,%5,%6,%7}, {%8,%9}, {%0,%1,%2,%3};\n"
        : "+f"(c[0]), "+f"(c[1]), "+f"(c[2]), "+f"(c[3])
        : "r"(a[0]), "r"(a[1]), "r"(a[2]), "r"(a[3]), "r"(b0), "r"(b1));
}
__device__ __forceinline__ uint32_t pack_h2(__half a, __half b) {
    __half2 h2 = __halves2half2(a, b);
    return *(uint32_t*)&h2;
}

// ---------------- GEMM: C[M,NT] = A[M,KT] @ W  (BM=128, BK=64) ----------------
// USE_LO: add Ah*Bl correction term. HALF_IN: A fp16; else fp32->fp16 in-flight.
template <int NT, int KT, bool HALF_IN, bool HALF_OUT, bool USE_LO>
__global__ void __launch_bounds__(256, 2)
gemm_hmma(const void* __restrict__ A, const __half* __restrict__ Bhi,
          const __half* __restrict__ Blo, void* __restrict__ C, int M) {
    constexpr int BK = 64;
    constexpr int ST = BK + 8;
    constexpr int WN = NT / 2;
    constexpr int NTILES = WN / 8;
    constexpr int CH = KT / BK;

    extern __shared__ __half sm[];
    __half* sAh = sm;                    // [128][ST]
    __half* sBh = sAh + 128 * ST;        // [NT][ST]
    __half* sBl = sBh + NT * ST;         // only if USE_LO

    const int tid = threadIdx.x;
    const int wid = tid >> 5, lane = tid & 31;
    const int wm = wid & 3, wn = wid >> 2;
    const int g = lane >> 2, t = lane & 3;
    const int row0 = blockIdx.x * 128;

    float acc[2][NTILES][4];
    #pragma unroll
    for (int mt = 0; mt < 2; ++mt)
        #pragma unroll
        for (int nt = 0; nt < NTILES; ++nt)
            #pragma unroll
            for (int q = 0; q < 4; ++q) acc[mt][nt][q] = 0.f;

    for (int c = 0; c < CH; ++c) {
        // ---- A tile into smem ----
        if (HALF_IN) {
            const __half* A16 = (const __half*)A;
            #pragma unroll
            for (int i = tid; i < 128 * 8; i += 256) {
                int r = i >> 3;
                int kq = (i & 7) << 3;
                uint4 v = make_uint4(0, 0, 0, 0);
                if (row0 + r < M)
                    v = *(const uint4*)(A16 + (size_t)(row0 + r) * KT + c * BK + kq);
                *(uint4*)(sAh + r * ST + kq) = v;
            }
        } else {
            const float* A32 = (const float*)A;
            #pragma unroll
            for (int i = tid; i < 128 * 16; i += 256) {
                int r = i >> 4;
                int kq = (i & 15) << 2;
                float4 v = make_float4(0.f, 0.f, 0.f, 0.f);
                if (row0 + r < M)
                    v = *(const float4*)(A32 + (size_t)(row0 + r) * KT + c * BK + kq);
                __half h0 = __float2half_rn(v.x), h1 = __float2half_rn(v.y);
                __half h2 = __float2half_rn(v.z), h3 = __float2half_rn(v.w);
                *(uint2*)(sAh + r * ST + kq) = make_uint2(pack_h2(h0, h1), pack_h2(h2, h3));
            }
        }
        // ---- B tiles ----
        #pragma unroll
        for (int i = tid; i < NT * 16; i += 256) {
            int n = i >> 4;
            int kq = (i & 15) << 2;
            *(uint2*)(sBh + n * ST + kq) =
                *(const uint2*)(Bhi + (size_t)n * KT + c * BK + kq);
            if (USE_LO)
                *(uint2*)(sBl + n * ST + kq) =
                    *(const uint2*)(Blo + (size_t)n * KT + c * BK + kq);
        }
        __syncthreads();

        #pragma unroll
        for (int kk = 0; kk < 4; ++kk) {
            const int k0 = kk * 16;
            uint32_t ah[2][4];
            #pragma unroll
            for (int mt = 0; mt < 2; ++mt) {
                int r = wm * 32 + mt * 16 + g;
                ah[mt][0] = *(uint32_t*)(sAh + r * ST + k0 + 2 * t);
                ah[mt][1] = *(uint32_t*)(sAh + (r + 8) * ST + k0 + 2 * t);
                ah[mt][2] = *(uint32_t*)(sAh + r * ST + k0 + 2 * t + 8);
                ah[mt][3] = *(uint32_t*)(sAh + (r + 8) * ST + k0 + 2 * t + 8);
            }
            #pragma unroll
            for (int nt = 0; nt < NTILES; ++nt) {
                int n = wn * WN + nt * 8 + g;
                uint32_t bh0 = *(uint32_t*)(sBh + n * ST + k0 + 2 * t);
                uint32_t bh1 = *(uint32_t*)(sBh + n * ST + k0 + 2 * t + 8);
                #pragma unroll
                for (int mt = 0; mt < 2; ++mt)
                    mma16816(acc[mt][nt], ah[mt], bh0, bh1);
                if (USE_LO) {
                    uint32_t bl0 = *(uint32_t*)(sBl + n * ST + k0 + 2 * t);
                    uint32_t bl1 = *(uint32_t*)(sBl + n * ST + k0 + 2 * t + 8);
                    #pragma unroll
                    for (int mt = 0; mt < 2; ++mt)
                        mma16816(acc[mt][nt], ah[mt], bl0, bl1);
                }
            }
        }
        __syncthreads();
    }

    #pragma unroll
    for (int mt = 0; mt < 2; ++mt) {
        int r = row0 + wm * 32 + mt * 16 + g;
        #pragma unroll
        for (int nt = 0; nt < NTILES; ++nt) {
            int col = wn * WN + nt * 8 + 2 * t;
            if (HALF_OUT) {
                __half* Ch = (__half*)C;
                if (r < M)
                    *(__half2*)(Ch + (size_t)r * NT + col) =
                        __floats2half2_rn(acc[mt][nt][0], acc[mt][nt][1]);
                if (r + 8 < M)
                    *(__half2*)(Ch + (size_t)(r + 8) * NT + col) =
                        __floats2half2_rn(acc[mt][nt][2], acc[mt][nt][3]);
            } else {
                float* Cf = (float*)C;
                if (r < M)
                    *(float2*)(Cf + (size_t)r * NT + col) =
                        make_float2(acc[mt][nt][0], acc[mt][nt][1]);
                if (r + 8 < M)
                    *(float2*)(Cf + (size_t)(r + 8) * NT + col) =
                        make_float2(acc[mt][nt][2], acc[mt][nt][3]);
            }
        }
    }
}

// ---------------- aggregation over fp16 H1: 2 nodes per warp (2x MLP) ----------------
__global__ void k_agg128h(const __half* __restrict__ H, const float* __restrict__ bias,
                          __half* __restrict__ out) {
    int warp = (blockIdx.x * blockDim.x + threadIdx.x) >> 5;
    int lane = threadIdx.x & 31;
    int n0 = warp * 2, n1 = warp * 2 + 1;
    if (n0 >= NN) return;
    bool has1 = (n1 < NN);
    int b0 = g_rowoff[n0], e0 = g_rowoff[n0 + 1];
    int b1 = has1 ? g_rowoff[n1] : 0, e1 = has1 ? g_rowoff[n1 + 1] : 0;
    const uint2* Hv = (const uint2*)H;

    float4 a0 = make_float4(0.f, 0.f, 0.f, 0.f);
    float4 a1 = make_float4(0.f, 0.f, 0.f, 0.f);
    int len = max(e0 - b0, e1 - b1);
    for (int j = 0; j < len; ++j) {
        int p0 = b0 + j, p1 = b1 + j;
        bool v0 = p0 < e0, v1 = p1 < e1;
        int s0i = v0 ? g_col[p0] : 0;
        int s1i = v1 ? g_col[p1] : 0;
        float w0 = v0 ? __ldg(&g_dinv[s0i]) : 0.f;
        float w1 = v1 ? __ldg(&g_dinv[s1i]) : 0.f;
        uint2 h0 = v0 ? __ldg(&Hv[(size_t)s0i * 32 + lane]) : make_uint2(0, 0);
        uint2 h1 = v1 ? __ldg(&Hv[(size_t)s1i * 32 + lane]) : make_uint2(0, 0);
        float2 q0 = __half22float2(*(__half2*)&h0.x);
        float2 q1 = __half22float2(*(__half2*)&h0.y);
        a0.x = fmaf(w0, q0.x, a0.x);
        a0.y = fmaf(w0, q0.y, a0.y);
        a0.z = fmaf(w0, q1.x, a0.z);
        a0.w = fmaf(w0, q1.y, a0.w);
        float2 r0 = __half22float2(*(__half2*)&h1.x);
        float2 r1 = __half22float2(*(__half2*)&h1.y);
        a1.x = fmaf(w1, r0.x, a1.x);
        a1.y = fmaf(w1, r0.y, a1.y);
        a1.z = fmaf(w1, r1.x, a1.z);
        a1.w = fmaf(w1, r1.y, a1.w);
    }
    float4 bb = ((const float4*)bias)[lane];
    {
        float di = g_dinv[n0], ws = di * di;
        uint2 sv = Hv[(size_t)n0 * 32 + lane];
        float2 s0 = __half22float2(*(__half2*)&sv.x);
        float2 s1 = __half22float2(*(__half2*)&sv.y);
        uint2 o;
        *(__half2*)&o.x = __floats2half2_rn(
            fmaxf(fmaf(di, a0.x, ws * s0.x) + bb.x, 0.f),
            fmaxf(fmaf(di, a0.y, ws * s0.y) + bb.y, 0.f));
        *(__half2*)&o.y = __floats2half2_rn(
            fmaxf(fmaf(di, a0.z, ws * s1.x) + bb.z, 0.f),
            fmaxf(fmaf(di, a0.w, ws * s1.y) + bb.w, 0.f));
        ((uint2*)out)[(size_t)n0 * 32 + lane] = o;
    }
    if (has1) {
        float di = g_dinv[n1], ws = di * di;
        uint2 sv = Hv[(size_t)n1 * 32 + lane];
        float2 s0 = __half22float2(*(__half2*)&sv.x);
        float2 s1 = __half22float2(*(__half2*)&sv.y);
        uint2 o;
        *(__half2*)&o.x = __floats2half2_rn(
            fmaxf(fmaf(di, a1.x, ws * s0.x) + bb.x, 0.f),
            fmaxf(fmaf(di, a1.y, ws * s0.y) + bb.y, 0.f));
        *(__half2*)&o.y = __floats2half2_rn(
            fmaxf(fmaf(di, a1.z, ws * s1.x) + bb.z, 0.f),
            fmaxf(fmaf(di, a1.w, ws * s1.y) + bb.w, 0.f));
        ((uint2*)out)[(size_t)n1 * 32 + lane] = o;
    }
}

// ---------------- final aggregation over fp16 H2: 2 nodes per warp ----------------
__global__ void k_agg64h(const __half* __restrict__ H, const float* __restrict__ bias,
                         float* __restrict__ out) {
    int warp = (blockIdx.x * blockDim.x + threadIdx.x) >> 5;
    int lane = threadIdx.x & 31;
    int n0 = warp * 2, n1 = warp * 2 + 1;
    if (n0 >= NN) return;
    bool has1 = (n1 < NN);
    int b0 = g_rowoff[n0], e0 = g_rowoff[n0 + 1];
    int b1 = has1 ? g_rowoff[n1] : 0, e1 = has1 ? g_rowoff[n1 + 1] : 0;
    const uint32_t* Hv = (const uint32_t*)H;

    float2 a0 = make_float2(0.f, 0.f);
    float2 a1 = make_float2(0.f, 0.f);
    int len = max(e0 - b0, e1 - b1);
    for (int j = 0; j < len; ++j) {
        int p0 = b0 + j, p1 = b1 + j;
        bool v0 = p0 < e0, v1 = p1 < e1;
        int s0i = v0 ? g_col[p0] : 0;
        int s1i = v1 ? g_col[p1] : 0;
        float w0 = v0 ? __ldg(&g_dinv[s0i]) : 0.f;
        float w1 = v1 ? __ldg(&g_dinv[s1i]) : 0.f;
        uint32_t h0 = v0 ? __ldg(&Hv[(size_t)s0i * 32 + lane]) : 0u;
        uint32_t h1 = v1 ? __ldg(&Hv[(size_t)s1i * 32 + lane]) : 0u;
        float2 q0 = __half22float2(*(__half2*)&h0);
        float2 q1 = __half22float2(*(__half2*)&h1);
        a0.x = fmaf(w0, q0.x, a0.x);
        a0.y = fmaf(w0, q0.y, a0.y);
        a1.x = fmaf(w1, q1.x, a1.x);
        a1.y = fmaf(w1, q1.y, a1.y);
    }
    float2 bb = ((const float2*)bias)[lane];
    {
        float di = g_dinv[n0], ws = di * di;
        uint32_t sv = Hv[(size_t)n0 * 32 + lane];
        float2 s = __half22float2(*(__half2*)&sv);
        float2 r;
        r.x = fmaf(di, a0.x, ws * s.x) + bb.x;
        r.y = fmaf(di, a0.y, ws * s.y) + bb.y;
        ((float2*)out)[(size_t)n0 * 32 + lane] = r;
    }
    if (has1) {
        float di = g_dinv[n1], ws = di * di;
        uint32_t sv = Hv[(size_t)n1 * 32 + lane];
        float2 s = __half22float2(*(__half2*)&sv);
        float2 r;
        r.x = fmaf(di, a1.x, ws * s.x) + bb.x;
        r.y = fmaf(di, a1.y, ws * s.y) + bb.y;
        ((float2*)out)[(size_t)n1 * 32 + lane] = r;
    }
}

// ---------------- launch ----------------
extern "C" void kernel_launch(void* const* d_in, const int* in_sizes, int n_in,
                              void* d_out, int out_size) {
    const float* x  = (const float*)d_in[0];
    const void*  ei = d_in[1];
    const float* W1 = (const float*)d_in[2];
    const float* b1 = (const float*)d_in[3];
    const float* W2 = (const float*)d_in[4];
    const float* b2 = (const float*)d_in[5];
    float* out = (float*)d_out;

    __half *H1h, *A1h, *H2h;
    __half *w1h, *w2h, *w2l;
    int *dfP;
    cudaGetSymbolAddress((void**)&H1h, g_H1h);
    cudaGetSymbolAddress((void**)&A1h, g_A1h);
    cudaGetSymbolAddress((void**)&H2h, g_H2h);
    cudaGetSymbolAddress((void**)&w1h, g_w1h);
    cudaGetSymbolAddress((void**)&w2h, g_w2h);
    cudaGetSymbolAddress((void**)&w2l, g_w2l);
    cudaGetSymbolAddress((void**)&dfP, g_degflag);

    constexpr int ST = 72;
    const int SM1 = (128 * ST + 128 * ST) * (int)sizeof(__half);           // 36864
    const int SM2 = (128 * ST + 64 * ST + 64 * ST) * (int)sizeof(__half);  // 36864
    cudaFuncSetAttribute((const void*)gemm_hmma<HID, IND, false, true, false>,
                         cudaFuncAttributeMaxDynamicSharedMemorySize, SM1);
    cudaFuncSetAttribute((const void*)gemm_hmma<OUTD, HID, true, true, true>,
                         cudaFuncAttributeMaxDynamicSharedMemorySize, SM2);

    const int TB = 256;
    const int gQ = (NE / 4 + TB - 1) / TB;
    const int gH = (NE / 2 + TB - 1) / TB;
    const int gM = (NN + 127) / 128;
    const int gAgg = ((NN + 1) / 2 * 32 + TB - 1) / TB;   // 2 nodes per warp

    cudaStream_t s2;
    cudaEvent_t evFork, evJoin;
    cudaStreamCreateWithFlags(&s2, cudaStreamNonBlocking);
    cudaEventCreateWithFlags(&evFork, cudaEventDisableTiming);
    cudaEventCreateWithFlags(&evJoin, cudaEventDisableTiming);

    cudaEventRecord(evFork, 0);
    cudaStreamWaitEvent(s2, evFork, 0);

    // ---- side stream: edge normalization + CSR build ----
    cudaMemsetAsync(dfP, 0, (NN + NBLK_SCAN) * sizeof(int), s2);
    k_convert_count4<<<gQ, TB, 0, s2>>>(ei);
    k_scan<<<NBLK_SCAN, 1024, 0, s2>>>();
    k_fill2<<<gH, TB, 0, s2>>>();
    cudaEventRecord(evJoin, s2);

    // ---- main stream: weight pack + layer-1 GEMM (independent of CSR) ----
    k_pack<<<(HID * IND + TB - 1) / TB, TB>>>(W1, W2);
    gemm_hmma<HID, IND, false, true, false><<<gM, 256, SM1>>>(x, w1h, nullptr, H1h, NN);

    // join: aggregation needs both CSR and H1
    cudaStreamWaitEvent(0, evJoin, 0);
    k_agg128h<<<gAgg, TB>>>(H1h, b1, A1h);

    // layer 2
    gemm_hmma<OUTD, HID, true, true, true><<<gM, 256, SM2>>>(A1h, w2h, w2l, H2h, NN);
    k_agg64h<<<gAgg, TB>>>(H2h, b2, out);
}

// round 14
// speedup vs baseline: 1.1215x; 1.1215x over previous
#include <cuda_runtime.h>
#include <cuda_fp16.h>
#include <cstdint>

// ---------------- problem constants ----------------
#define NN 50000          // nodes
#define NE 800000         // edges
#define IND 256
#define HID 128
#define OUTD 64

// ---------------- device scratch (no allocation allowed) ----------------
__device__ __align__(128) int    g_deg[NN];
__device__ __align__(128) float  g_dinv[NN];
__device__ __align__(128) int    g_rowoff[NN + 1];
__device__ __align__(128) int    g_src[NE];
__device__ __align__(128) int    g_dst[NE];
__device__ __align__(128) int    g_rank[NE];
__device__ __align__(128) int    g_col[NE];
__device__ __align__(128) float  g_ew[NE];                  // dinv[src] per CSR slot
__device__ __align__(128) __half g_H1h[(size_t)NN * HID];  // x @ W1, fp16
__device__ __align__(128) float  g_A1[(size_t)NN * HID];   // relu(agg(H1)+b1)
__device__ __align__(128) __half g_H2h[(size_t)NN * OUTD]; // A1 @ W2, fp16
__device__ int g_is64;

#define NBLK_SCAN 49      // ceil(50000/1024)
__device__ int g_bflag[NBLK_SCAN];   // 0 = not ready, else block_sum + 1

// fp16 weight images, n-major: img[n][k] (col-major B for mma.row.col)
__device__ __align__(128) __half g_w1h[HID * IND];          // W1 hi only (fp16 GEMM1)
__device__ __align__(128) __half g_w2h[OUTD * HID];
__device__ __align__(128) __half g_w2l[OUTD * HID];

// ---------------- edge dtype detection (1 warp, ballot) ----------------
__global__ void k_detect(const int* __restrict__ e32) {
    unsigned b = __ballot_sync(~0u, e32[threadIdx.x * 2 + 1] != 0);
    if (threadIdx.x == 0) g_is64 = (b == 0) ? 1 : 0;
}

// fused convert + degree count + per-edge rank, 4 edges/thread
__global__ void k_convert_count4(const void* __restrict__ edges) {
    int q = blockIdx.x * blockDim.x + threadIdx.x;   // quad index
    if (q >= NE / 4) return;
    int s0, s1, s2, s3, d0, d1, d2, d3;
    if (g_is64) {
        const longlong2* p = (const longlong2*)edges;
        const longlong2* pd = p + NE / 2;
        longlong2 a = p[q * 2], b = p[q * 2 + 1];
        longlong2 c = pd[q * 2], e = pd[q * 2 + 1];
        s0 = (int)a.x; s1 = (int)a.y; s2 = (int)b.x; s3 = (int)b.y;
        d0 = (int)c.x; d1 = (int)c.y; d2 = (int)e.x; d3 = (int)e.y;
    } else {
        const int4* p = (const int4*)edges;
        const int4* pd = p + NE / 4;
        int4 a = p[q], c = pd[q];
        s0 = a.x; s1 = a.y; s2 = a.z; s3 = a.w;
        d0 = c.x; d1 = c.y; d2 = c.z; d3 = c.w;
    }
    *(int4*)&g_src[q * 4] = make_int4(s0, s1, s2, s3);
    *(int4*)&g_dst[q * 4] = make_int4(d0, d1, d2, d3);
    int r0 = atomicAdd(&g_deg[d0], 1);
    int r1 = atomicAdd(&g_deg[d1], 1);
    int r2 = atomicAdd(&g_deg[d2], 1);
    int r3 = atomicAdd(&g_deg[d3], 1);
    *(int4*)&g_rank[q * 4] = make_int4(r0, r1, r2, r3);
}

// ---------------- single-kernel scan (decoupled lookback) + dinv ----------------
__global__ void __launch_bounds__(1024) k_scan() {
    __shared__ int wsum[32];
    __shared__ int s_prefix;
    const int tid = threadIdx.x, lane = tid & 31, wid = tid >> 5;
    const int bid = blockIdx.x;
    const int i = bid * 1024 + tid;

    int v = (i < NN) ? g_deg[i] : 0;
    if (i < NN) g_dinv[i] = rsqrtf((float)(v + 1));

    int incl = v;
    #pragma unroll
    for (int o = 1; o < 32; o <<= 1) {
        int t = __shfl_up_sync(~0u, incl, o);
        if (lane >= o) incl += t;
    }
    if (lane == 31) wsum[wid] = incl;
    if (tid == 0) s_prefix = 0;
    __syncthreads();
    if (wid == 0) {
        int w = wsum[lane];
        #pragma unroll
        for (int o = 1; o < 32; o <<= 1) {
            int t = __shfl_up_sync(~0u, w, o);
            if (lane >= o) w += t;
        }
        wsum[lane] = w;
    }
    __syncthreads();
    if (wid > 0) incl += wsum[wid - 1];
    const int bsum = wsum[31];

    if (tid == 0) atomicExch(&g_bflag[bid], bsum + 1);   // value embedded in flag
    if (tid < bid) {
        int f;
        do { f = atomicAdd(&g_bflag[tid], 0); } while (f == 0);
        atomicAdd_block(&s_prefix, f - 1);
    }
    __syncthreads();
    const int excl = s_prefix + incl - v;
    if (i < NN) g_rowoff[i] = excl;
    if (i == NN - 1) g_rowoff[NN] = excl + v;
}

// CSR fill, atomic-free: slot = rowoff[dst] + rank; also store edge weight dinv[src]
__global__ void k_fill4() {
    int q = blockIdx.x * blockDim.x + threadIdx.x;
    if (q >= NE / 4) return;
    int4 s = *(const int4*)&g_src[q * 4];
    int4 d = *(const int4*)&g_dst[q * 4];
    int4 r = *(const int4*)&g_rank[q * 4];
    int p0 = __ldg(&g_rowoff[d.x]) + r.x;
    int p1 = __ldg(&g_rowoff[d.y]) + r.y;
    int p2 = __ldg(&g_rowoff[d.z]) + r.z;
    int p3 = __ldg(&g_rowoff[d.w]) + r.w;
    g_col[p0] = s.x;
    g_col[p1] = s.y;
    g_col[p2] = s.z;
    g_col[p3] = s.w;
    g_ew[p0] = __ldg(&g_dinv[s.x]);
    g_ew[p1] = __ldg(&g_dinv[s.y]);
    g_ew[p2] = __ldg(&g_dinv[s.z]);
    g_ew[p3] = __ldg(&g_dinv[s.w]);
}

// ---------------- weight pack (output-coalesced) ----------------
__global__ void k_pack(const float* __restrict__ W1, const float* __restrict__ W2) {
    int i = blockIdx.x * blockDim.x + threadIdx.x;
    if (i < HID * IND) {                 // out index: n*IND + k
        int n = i / IND, k = i % IND;
        g_w1h[i] = __float2half_rn(__ldg(&W1[k * HID + n]));
    }
    if (i < OUTD * HID) {                // out index: n*HID + k
        int n = i / HID, k = i % HID;
        float v = __ldg(&W2[k * OUTD + n]);
        __half h = __float2half_rn(v);
        __half l = __float2half_rn(v - __half2float(h));
        g_w2h[i] = h;
        g_w2l[i] = l;
    }
}

// ---------------- HMMA primitives ----------------
__device__ __forceinline__ void mma16816(float* c, const uint32_t* a,
                                         uint32_t b0, uint32_t b1) {
    asm volatile(
        "mma.sync.aligned.m16n8k16.row.col.f32.f16.f16.f32 "
        "{%0,%1,%2,%3}, {%4,%5,%6,%7}, {%8,%9}, {%0,%1,%2,%3};\n"
        : "+f"(c[0]), "+f"(c[1]), "+f"(c[2]), "+f"(c[3])
        : "r"(a[0]), "r"(a[1]), "r"(a[2]), "r"(a[3]), "r"(b0), "r"(b1));
}
__device__ __forceinline__ uint32_t pack_h2(__half a, __half b) {
    __half2 h2 = __halves2half2(a, b);
    return *(uint32_t*)&h2;
}

// ---------------- GEMM: C[M,NT] = A[M,KT] @ W  (BM=128, BK=64) ----------------
// USE_LO: add Ah*Bl correction. fp32 A converted in-flight; HALF_OUT controls C dtype.
template <int NT, int KT, bool HALF_OUT, bool USE_LO>
__global__ void __launch_bounds__(256, 2)
gemm_hmma(const float* __restrict__ A, const __half* __restrict__ Bhi,
          const __half* __restrict__ Blo, void* __restrict__ C, int M) {
    constexpr int BK = 64;
    constexpr int ST = BK + 8;
    constexpr int WN = NT / 2;
    constexpr int NTILES = WN / 8;
    constexpr int CH = KT / BK;

    extern __shared__ __half sm[];
    __half* sAh = sm;                    // [128][ST]
    __half* sBh = sAh + 128 * ST;        // [NT][ST]
    __half* sBl = sBh + NT * ST;         // only if USE_LO

    const int tid = threadIdx.x;
    const int wid = tid >> 5, lane = tid & 31;
    const int wm = wid & 3, wn = wid >> 2;
    const int g = lane >> 2, t = lane & 3;
    const int row0 = blockIdx.x * 128;

    float acc[2][NTILES][4];
    #pragma unroll
    for (int mt = 0; mt < 2; ++mt)
        #pragma unroll
        for (int nt = 0; nt < NTILES; ++nt)
            #pragma unroll
            for (int q = 0; q < 4; ++q) acc[mt][nt][q] = 0.f;

    for (int c = 0; c < CH; ++c) {
        #pragma unroll
        for (int i = tid; i < 128 * 16; i += 256) {
            int r = i >> 4;
            int kq = (i & 15) << 2;
            float4 v = make_float4(0.f, 0.f, 0.f, 0.f);
            if (row0 + r < M)
                v = *(const float4*)(A + (size_t)(row0 + r) * KT + c * BK + kq);
            __half h0 = __float2half_rn(v.x), h1 = __float2half_rn(v.y);
            __half h2 = __float2half_rn(v.z), h3 = __float2half_rn(v.w);
            *(uint2*)(sAh + r * ST + kq) = make_uint2(pack_h2(h0, h1), pack_h2(h2, h3));
        }
        #pragma unroll
        for (int i = tid; i < NT * 16; i += 256) {
            int n = i >> 4;
            int kq = (i & 15) << 2;
            *(uint2*)(sBh + n * ST + kq) =
                *(const uint2*)(Bhi + (size_t)n * KT + c * BK + kq);
            if (USE_LO)
                *(uint2*)(sBl + n * ST + kq) =
                    *(const uint2*)(Blo + (size_t)n * KT + c * BK + kq);
        }
        __syncthreads();

        #pragma unroll
        for (int kk = 0; kk < 4; ++kk) {
            const int k0 = kk * 16;
            uint32_t ah[2][4];
            #pragma unroll
            for (int mt = 0; mt < 2; ++mt) {
                int r = wm * 32 + mt * 16 + g;
                ah[mt][0] = *(uint32_t*)(sAh + r * ST + k0 + 2 * t);
                ah[mt][1] = *(uint32_t*)(sAh + (r + 8) * ST + k0 + 2 * t);
                ah[mt][2] = *(uint32_t*)(sAh + r * ST + k0 + 2 * t + 8);
                ah[mt][3] = *(uint32_t*)(sAh + (r + 8) * ST + k0 + 2 * t + 8);
            }
            #pragma unroll
            for (int nt = 0; nt < NTILES; ++nt) {
                int n = wn * WN + nt * 8 + g;
                uint32_t bh0 = *(uint32_t*)(sBh + n * ST + k0 + 2 * t);
                uint32_t bh1 = *(uint32_t*)(sBh + n * ST + k0 + 2 * t + 8);
                #pragma unroll
                for (int mt = 0; mt < 2; ++mt)
                    mma16816(acc[mt][nt], ah[mt], bh0, bh1);
                if (USE_LO) {
                    uint32_t bl0 = *(uint32_t*)(sBl + n * ST + k0 + 2 * t);
                    uint32_t bl1 = *(uint32_t*)(sBl + n * ST + k0 + 2 * t + 8);
                    #pragma unroll
                    for (int mt = 0; mt < 2; ++mt)
                        mma16816(acc[mt][nt], ah[mt], bl0, bl1);
                }
            }
        }
        __syncthreads();
    }

    #pragma unroll
    for (int mt = 0; mt < 2; ++mt) {
        int r = row0 + wm * 32 + mt * 16 + g;
        #pragma unroll
        for (int nt = 0; nt < NTILES; ++nt) {
            int col = wn * WN + nt * 8 + 2 * t;
            if (HALF_OUT) {
                __half* Ch = (__half*)C;
                if (r < M)
                    *(__half2*)(Ch + (size_t)r * NT + col) =
                        __floats2half2_rn(acc[mt][nt][0], acc[mt][nt][1]);
                if (r + 8 < M)
                    *(__half2*)(Ch + (size_t)(r + 8) * NT + col) =
                        __floats2half2_rn(acc[mt][nt][2], acc[mt][nt][3]);
            } else {
                float* Cf = (float*)C;
                if (r < M)
                    *(float2*)(Cf + (size_t)r * NT + col) =
                        make_float2(acc[mt][nt][0], acc[mt][nt][1]);
                if (r + 8 < M)
                    *(float2*)(Cf + (size_t)(r + 8) * NT + col) =
                        make_float2(acc[mt][nt][2], acc[mt][nt][3]);
            }
        }
    }
}

// ---------------- aggregation over fp16 H1: warp per node (ew streaming) ----------------
__global__ void k_agg128h(const __half* __restrict__ H, const float* __restrict__ bias,
                          float* __restrict__ out) {
    int warp = (blockIdx.x * blockDim.x + threadIdx.x) >> 5;
    int lane = threadIdx.x & 31;
    if (warp >= NN) return;
    int beg = g_rowoff[warp], end = g_rowoff[warp + 1];
    const uint2* Hv = (const uint2*)H;
    float4 acc = make_float4(0.f, 0.f, 0.f, 0.f);
    #pragma unroll 4
    for (int e = beg; e < end; ++e) {
        int s = g_col[e];
        float w = __ldg(&g_ew[e]);
        uint2 hv = __ldg(&Hv[(size_t)s * 32 + lane]);
        float2 p0 = __half22float2(*(__half2*)&hv.x);
        float2 p1 = __half22float2(*(__half2*)&hv.y);
        acc.x = fmaf(w, p0.x, acc.x);
        acc.y = fmaf(w, p0.y, acc.y);
        acc.z = fmaf(w, p1.x, acc.z);
        acc.w = fmaf(w, p1.y, acc.w);
    }
    float di = g_dinv[warp];
    float ws = di * di;
    uint2 sv = Hv[(size_t)warp * 32 + lane];
    float2 s0 = __half22float2(*(__half2*)&sv.x);
    float2 s1 = __half22float2(*(__half2*)&sv.y);
    float4 b = ((const float4*)bias)[lane];
    float4 r;
    r.x = fmaxf(fmaf(di, acc.x, ws * s0.x) + b.x, 0.f);
    r.y = fmaxf(fmaf(di, acc.y, ws * s0.y) + b.y, 0.f);
    r.z = fmaxf(fmaf(di, acc.z, ws * s1.x) + b.z, 0.f);
    r.w = fmaxf(fmaf(di, acc.w, ws * s1.y) + b.w, 0.f);
    ((float4*)out)[(size_t)warp * 32 + lane] = r;
}

// ---------------- final aggregation over fp16 H2 (64 cols, ew streaming) ----------------
__global__ void k_agg64h(const __half* __restrict__ H, const float* __restrict__ bias,
                         float* __restrict__ out) {
    int warp = (blockIdx.x * blockDim.x + threadIdx.x) >> 5;
    int lane = threadIdx.x & 31;
    if (warp >= NN) return;
    int beg = g_rowoff[warp], end = g_rowoff[warp + 1];
    const uint32_t* Hv = (const uint32_t*)H;
    float2 acc = make_float2(0.f, 0.f);
    #pragma unroll 4
    for (int e = beg; e < end; ++e) {
        int s = g_col[e];
        float w = __ldg(&g_ew[e]);
        uint32_t hv = __ldg(&Hv[(size_t)s * 32 + lane]);
        float2 h = __half22float2(*(__half2*)&hv);
        acc.x = fmaf(w, h.x, acc.x);
        acc.y = fmaf(w, h.y, acc.y);
    }
    float di = g_dinv[warp];
    float ws = di * di;
    uint32_t sv = Hv[(size_t)warp * 32 + lane];
    float2 self = __half22float2(*(__half2*)&sv);
    float2 b = ((const float2*)bias)[lane];
    float2 r;
    r.x = fmaf(di, acc.x, ws * self.x) + b.x;
    r.y = fmaf(di, acc.y, ws * self.y) + b.y;
    ((float2*)out)[(size_t)warp * 32 + lane] = r;
}

// ---------------- launch ----------------
extern "C" void kernel_launch(void* const* d_in, const int* in_sizes, int n_in,
                              void* d_out, int out_size) {
    const float* x  = (const float*)d_in[0];
    const void*  ei = d_in[1];
    const float* W1 = (const float*)d_in[2];
    const float* b1 = (const float*)d_in[3];
    const float* W2 = (const float*)d_in[4];
    const float* b2 = (const float*)d_in[5];
    float* out = (float*)d_out;

    __half *H1h, *H2h;
    float *A1;
    __half *w1h, *w2h, *w2l;
    int *degP, *flagP;
    cudaGetSymbolAddress((void**)&H1h, g_H1h);
    cudaGetSymbolAddress((void**)&H2h, g_H2h);
    cudaGetSymbolAddress((void**)&A1, g_A1);
    cudaGetSymbolAddress((void**)&w1h, g_w1h);
    cudaGetSymbolAddress((void**)&w2h, g_w2h);
    cudaGetSymbolAddress((void**)&w2l, g_w2l);
    cudaGetSymbolAddress((void**)&degP, g_deg);
    cudaGetSymbolAddress((void**)&flagP, g_bflag);

    constexpr int ST = 72;
    const int SM1 = (128 * ST + 128 * ST) * (int)sizeof(__half);            // 36864
    const int SM2 = (128 * ST + 64 * ST + 64 * ST) * (int)sizeof(__half);   // 36864
    cudaFuncSetAttribute((const void*)gemm_hmma<HID, IND, true, false>,
                         cudaFuncAttributeMaxDynamicSharedMemorySize, SM1);
    cudaFuncSetAttribute((const void*)gemm_hmma<OUTD, HID, true, true>,
                         cudaFuncAttributeMaxDynamicSharedMemorySize, SM2);

    const int TB = 256;
    const int gQ = (NE / 4 + TB - 1) / TB;
    const int gM = (NN + 127) / 128;

    cudaStream_t s2;
    cudaEvent_t evFork, evJoin;
    cudaStreamCreateWithFlags(&s2, cudaStreamNonBlocking);
    cudaEventCreateWithFlags(&evFork, cudaEventDisableTiming);
    cudaEventCreateWithFlags(&evJoin, cudaEventDisableTiming);

    cudaEventRecord(evFork, 0);
    cudaStreamWaitEvent(s2, evFork, 0);

    // ---- side stream: edge normalization + CSR build ----
    k_detect<<<1, 32, 0, s2>>>((const int*)ei);
    cudaMemsetAsync(degP, 0, NN * sizeof(int), s2);
    cudaMemsetAsync(flagP, 0, NBLK_SCAN * sizeof(int), s2);
    k_convert_count4<<<gQ, TB, 0, s2>>>(ei);
    k_scan<<<NBLK_SCAN, 1024, 0, s2>>>();
    k_fill4<<<gQ, TB, 0, s2>>>();
    cudaEventRecord(evJoin, s2);

    // ---- main stream: weight pack + layer-1 GEMM (independent of CSR) ----
    k_pack<<<(HID * IND + TB - 1) / TB, TB>>>(W1, W2);
    gemm_hmma<HID, IND, true, false><<<gM, 256, SM1>>>(x, w1h, nullptr, H1h, NN);

    // join: aggregation needs both CSR and H1
    cudaStreamWaitEvent(0, evJoin, 0);
    k_agg128h<<<(NN * 32 + TB - 1) / TB, TB>>>(H1h, b1, A1);

    // layer 2
    gemm_hmma<OUTD, HID, true, true><<<gM, 256, SM2>>>(A1, w2h, w2l, H2h, NN);
    k_agg64h<<<(NN * 32 + TB - 1) / TB, TB>>>(H2h, b2, out);
}

// round 15
// speedup vs baseline: 1.1952x; 1.0657x over previous
#include <cuda_runtime.h>
#include <cuda_fp16.h>
#include <cstdint>

// ---------------- problem constants ----------------
#define NN 50000          // nodes
#define NE 800000         // edges
#define IND 256
#define HID 128
#define OUTD 64

// ---------------- device scratch (no allocation allowed) ----------------
__device__ __align__(128) int    g_deg[NN];
__device__ __align__(128) float  g_dinv[NN];
__device__ __align__(128) int    g_rowoff[NN + 1];
__device__ __align__(128) int    g_src[NE];
__device__ __align__(128) int    g_dst[NE];
__device__ __align__(128) int    g_rank[NE];
__device__ __align__(128) int    g_col[NE];
__device__ __align__(128) __half g_H1h[(size_t)NN * HID];  // x @ W1, fp16
__device__ __align__(128) float  g_A1[(size_t)NN * HID];   // relu(agg(H1)+b1)
__device__ __align__(128) __half g_H2h[(size_t)NN * OUTD]; // A1 @ W2, fp16
__device__ int g_is64;

#define NBLK_SCAN 49      // ceil(50000/1024)
__device__ int g_bflag[NBLK_SCAN];   // 0 = not ready, else block_sum + 1

// fp16 weight images, n-major: img[n][k] (col-major B for mma.row.col)
__device__ __align__(128) __half g_w1h[HID * IND];          // W1 hi only (fp16 GEMM1)
__device__ __align__(128) __half g_w2h[OUTD * HID];
__device__ __align__(128) __half g_w2l[OUTD * HID];

// ---------------- edge dtype detection (1 warp, ballot) ----------------
__global__ void k_detect(const int* __restrict__ e32) {
    unsigned b = __ballot_sync(~0u, e32[threadIdx.x * 2 + 1] != 0);
    if (threadIdx.x == 0) g_is64 = (b == 0) ? 1 : 0;
}

// fused convert + degree count + per-edge rank, 4 edges/thread
__global__ void k_convert_count4(const void* __restrict__ edges) {
    int q = blockIdx.x * blockDim.x + threadIdx.x;   // quad index
    if (q >= NE / 4) return;
    int s0, s1, s2, s3, d0, d1, d2, d3;
    if (g_is64) {
        const longlong2* p = (const longlong2*)edges;
        const longlong2* pd = p + NE / 2;
        longlong2 a = p[q * 2], b = p[q * 2 + 1];
        longlong2 c = pd[q * 2], e = pd[q * 2 + 1];
        s0 = (int)a.x; s1 = (int)a.y; s2 = (int)b.x; s3 = (int)b.y;
        d0 = (int)c.x; d1 = (int)c.y; d2 = (int)e.x; d3 = (int)e.y;
    } else {
        const int4* p = (const int4*)edges;
        const int4* pd = p + NE / 4;
        int4 a = p[q], c = pd[q];
        s0 = a.x; s1 = a.y; s2 = a.z; s3 = a.w;
        d0 = c.x; d1 = c.y; d2 = c.z; d3 = c.w;
    }
    *(int4*)&g_src[q * 4] = make_int4(s0, s1, s2, s3);
    *(int4*)&g_dst[q * 4] = make_int4(d0, d1, d2, d3);
    int r0 = atomicAdd(&g_deg[d0], 1);
    int r1 = atomicAdd(&g_deg[d1], 1);
    int r2 = atomicAdd(&g_deg[d2], 1);
    int r3 = atomicAdd(&g_deg[d3], 1);
    *(int4*)&g_rank[q * 4] = make_int4(r0, r1, r2, r3);
}

// ---------------- single-kernel scan (decoupled lookback) + dinv ----------------
__global__ void __launch_bounds__(1024) k_scan() {
    __shared__ int wsum[32];
    __shared__ int s_prefix;
    const int tid = threadIdx.x, lane = tid & 31, wid = tid >> 5;
    const int bid = blockIdx.x;
    const int i = bid * 1024 + tid;

    int v = (i < NN) ? g_deg[i] : 0;
    if (i < NN) g_dinv[i] = rsqrtf((float)(v + 1));

    int incl = v;
    #pragma unroll
    for (int o = 1; o < 32; o <<= 1) {
        int t = __shfl_up_sync(~0u, incl, o);
        if (lane >= o) incl += t;
    }
    if (lane == 31) wsum[wid] = incl;
    if (tid == 0) s_prefix = 0;
    __syncthreads();
    if (wid == 0) {
        int w = wsum[lane];
        #pragma unroll
        for (int o = 1; o < 32; o <<= 1) {
            int t = __shfl_up_sync(~0u, w, o);
            if (lane >= o) w += t;
        }
        wsum[lane] = w;
    }
    __syncthreads();
    if (wid > 0) incl += wsum[wid - 1];
    const int bsum = wsum[31];

    if (tid == 0) atomicExch(&g_bflag[bid], bsum + 1);   // value embedded in flag
    if (tid < bid) {
        int f;
        do { f = atomicAdd(&g_bflag[tid], 0); } while (f == 0);
        atomicAdd_block(&s_prefix, f - 1);
    }
    __syncthreads();
    const int excl = s_prefix + incl - v;
    if (i < NN) g_rowoff[i] = excl;
    if (i == NN - 1) g_rowoff[NN] = excl + v;
}

// CSR fill, atomic-free, 2 edges/thread (col only — no ew)
__global__ void k_fill2() {
    int q = blockIdx.x * blockDim.x + threadIdx.x;
    if (q >= NE / 2) return;
    int2 s = *(const int2*)&g_src[q * 2];
    int2 d = *(const int2*)&g_dst[q * 2];
    int2 r = *(const int2*)&g_rank[q * 2];
    g_col[__ldg(&g_rowoff[d.x]) + r.x] = s.x;
    g_col[__ldg(&g_rowoff[d.y]) + r.y] = s.y;
}

// ---------------- weight pack (output-coalesced) ----------------
__global__ void k_pack(const float* __restrict__ W1, const float* __restrict__ W2) {
    int i = blockIdx.x * blockDim.x + threadIdx.x;
    if (i < HID * IND) {                 // out index: n*IND + k
        int n = i / IND, k = i % IND;
        g_w1h[i] = __float2half_rn(__ldg(&W1[k * HID + n]));
    }
    if (i < OUTD * HID) {                // out index: n*HID + k
        int n = i / HID, k = i % HID;
        float v = __ldg(&W2[k * OUTD + n]);
        __half h = __float2half_rn(v);
        __half l = __float2half_rn(v - __half2float(h));
        g_w2h[i] = h;
        g_w2l[i] = l;
    }
}

// ---------------- HMMA primitives ----------------
__device__ __forceinline__ void mma16816(float* c, const uint32_t* a,
                                         uint32_t b0, uint32_t b1) {
    asm volatile(
        "mma.sync.aligned.m16n8k16.row.col.f32.f16.f16.f32 "
        "{%0,%1,%2,%3}, {%4,%5,%6,%7}, {%8,%9}, {%0,%1,%2,%3};\n"
        : "+f"(c[0]), "+f"(c[1]), "+f"(c[2]), "+f"(c[3])
        : "r"(a[0]), "r"(a[1]), "r"(a[2]), "r"(a[3]), "r"(b0), "r"(b1));
}
__device__ __forceinline__ uint32_t pack_h2(__half a, __half b) {
    __half2 h2 = __halves2half2(a, b);
    return *(uint32_t*)&h2;
}

// ---------------- GEMM: C[M,NT] = A[M,KT] @ W  (BM=128, BK=64) ----------------
// USE_LO: add Ah*Bl correction. fp32 A converted in-flight; HALF_OUT controls C dtype.
template <int NT, int KT, bool HALF_OUT, bool USE_LO>
__global__ void __launch_bounds__(256, 2)
gemm_hmma(const float* __restrict__ A, const __half* __restrict__ Bhi,
          const __half* __restrict__ Blo, void* __restrict__ C, int M) {
    constexpr int BK = 64;
    constexpr int ST = BK + 8;
    constexpr int WN = NT / 2;
    constexpr int NTILES = WN / 8;
    constexpr int CH = KT / BK;

    extern __shared__ __half sm[];
    __half* sAh = sm;                    // [128][ST]
    __half* sBh = sAh + 128 * ST;        // [NT][ST]
    __half* sBl = sBh + NT * ST;         // only if USE_LO

    const int tid = threadIdx.x;
    const int wid = tid >> 5, lane = tid & 31;
    const int wm = wid & 3, wn = wid >> 2;
    const int g = lane >> 2, t = lane & 3;
    const int row0 = blockIdx.x * 128;

    float acc[2][NTILES][4];
    #pragma unroll
    for (int mt = 0; mt < 2; ++mt)
        #pragma unroll
        for (int nt = 0; nt < NTILES; ++nt)
            #pragma unroll
            for (int q = 0; q < 4; ++q) acc[mt][nt][q] = 0.f;

    for (int c = 0; c < CH; ++c) {
        #pragma unroll
        for (int i = tid; i < 128 * 16; i += 256) {
            int r = i >> 4;
            int kq = (i & 15) << 2;
            float4 v = make_float4(0.f, 0.f, 0.f, 0.f);
            if (row0 + r < M)
                v = *(const float4*)(A + (size_t)(row0 + r) * KT + c * BK + kq);
            __half h0 = __float2half_rn(v.x), h1 = __float2half_rn(v.y);
            __half h2 = __float2half_rn(v.z), h3 = __float2half_rn(v.w);
            *(uint2*)(sAh + r * ST + kq) = make_uint2(pack_h2(h0, h1), pack_h2(h2, h3));
        }
        #pragma unroll
        for (int i = tid; i < NT * 16; i += 256) {
            int n = i >> 4;
            int kq = (i & 15) << 2;
            *(uint2*)(sBh + n * ST + kq) =
                *(const uint2*)(Bhi + (size_t)n * KT + c * BK + kq);
            if (USE_LO)
                *(uint2*)(sBl + n * ST + kq) =
                    *(const uint2*)(Blo + (size_t)n * KT + c * BK + kq);
        }
        __syncthreads();

        #pragma unroll
        for (int kk = 0; kk < 4; ++kk) {
            const int k0 = kk * 16;
            uint32_t ah[2][4];
            #pragma unroll
            for (int mt = 0; mt < 2; ++mt) {
                int r = wm * 32 + mt * 16 + g;
                ah[mt][0] = *(uint32_t*)(sAh + r * ST + k0 + 2 * t);
                ah[mt][1] = *(uint32_t*)(sAh + (r + 8) * ST + k0 + 2 * t);
                ah[mt][2] = *(uint32_t*)(sAh + r * ST + k0 + 2 * t + 8);
                ah[mt][3] = *(uint32_t*)(sAh + (r + 8) * ST + k0 + 2 * t + 8);
            }
            #pragma unroll
            for (int nt = 0; nt < NTILES; ++nt) {
                int n = wn * WN + nt * 8 + g;
                uint32_t bh0 = *(uint32_t*)(sBh + n * ST + k0 + 2 * t);
                uint32_t bh1 = *(uint32_t*)(sBh + n * ST + k0 + 2 * t + 8);
                #pragma unroll
                for (int mt = 0; mt < 2; ++mt)
                    mma16816(acc[mt][nt], ah[mt], bh0, bh1);
                if (USE_LO) {
                    uint32_t bl0 = *(uint32_t*)(sBl + n * ST + k0 + 2 * t);
                    uint32_t bl1 = *(uint32_t*)(sBl + n * ST + k0 + 2 * t + 8);
                    #pragma unroll
                    for (int mt = 0; mt < 2; ++mt)
                        mma16816(acc[mt][nt], ah[mt], bl0, bl1);
                }
            }
        }
        __syncthreads();
    }

    #pragma unroll
    for (int mt = 0; mt < 2; ++mt) {
        int r = row0 + wm * 32 + mt * 16 + g;
        #pragma unroll
        for (int nt = 0; nt < NTILES; ++nt) {
            int col = wn * WN + nt * 8 + 2 * t;
            if (HALF_OUT) {
                __half* Ch = (__half*)C;
                if (r < M)
                    *(__half2*)(Ch + (size_t)r * NT + col) =
                        __floats2half2_rn(acc[mt][nt][0], acc[mt][nt][1]);
                if (r + 8 < M)
                    *(__half2*)(Ch + (size_t)(r + 8) * NT + col) =
                        __floats2half2_rn(acc[mt][nt][2], acc[mt][nt][3]);
            } else {
                float* Cf = (float*)C;
                if (r < M)
                    *(float2*)(Cf + (size_t)r * NT + col) =
                        make_float2(acc[mt][nt][0], acc[mt][nt][1]);
                if (r + 8 < M)
                    *(float2*)(Cf + (size_t)(r + 8) * NT + col) =
                        make_float2(acc[mt][nt][2], acc[mt][nt][3]);
            }
        }
    }
}

// ---------------- aggregation over fp16 H1: warp per node ----------------
__global__ void k_agg128h(const __half* __restrict__ H, const float* __restrict__ bias,
                          float* __restrict__ out) {
    int warp = (blockIdx.x * blockDim.x + threadIdx.x) >> 5;
    int lane = threadIdx.x & 31;
    if (warp >= NN) return;
    int beg = g_rowoff[warp], end = g_rowoff[warp + 1];
    const uint2* Hv = (const uint2*)H;
    float4 acc = make_float4(0.f, 0.f, 0.f, 0.f);
    #pragma unroll 4
    for (int e = beg; e < end; ++e) {
        int s = g_col[e];
        float w = __ldg(&g_dinv[s]);
        uint2 hv = __ldg(&Hv[(size_t)s * 32 + lane]);
        float2 p0 = __half22float2(*(__half2*)&hv.x);
        float2 p1 = __half22float2(*(__half2*)&hv.y);
        acc.x = fmaf(w, p0.x, acc.x);
        acc.y = fmaf(w, p0.y, acc.y);
        acc.z = fmaf(w, p1.x, acc.z);
        acc.w = fmaf(w, p1.y, acc.w);
    }
    float di = g_dinv[warp];
    float ws = di * di;
    uint2 sv = Hv[(size_t)warp * 32 + lane];
    float2 s0 = __half22float2(*(__half2*)&sv.x);
    float2 s1 = __half22float2(*(__half2*)&sv.y);
    float4 b = ((const float4*)bias)[lane];
    float4 r;
    r.x = fmaxf(fmaf(di, acc.x, ws * s0.x) + b.x, 0.f);
    r.y = fmaxf(fmaf(di, acc.y, ws * s0.y) + b.y, 0.f);
    r.z = fmaxf(fmaf(di, acc.z, ws * s1.x) + b.z, 0.f);
    r.w = fmaxf(fmaf(di, acc.w, ws * s1.y) + b.w, 0.f);
    ((float4*)out)[(size_t)warp * 32 + lane] = r;
}

// ---------------- final aggregation over fp16 H2 (64 cols) ----------------
__global__ void k_agg64h(const __half* __restrict__ H, const float* __restrict__ bias,
                         float* __restrict__ out) {
    int warp = (blockIdx.x * blockDim.x + threadIdx.x) >> 5;
    int lane = threadIdx.x & 31;
    if (warp >= NN) return;
    int beg = g_rowoff[warp], end = g_rowoff[warp + 1];
    const uint32_t* Hv = (const uint32_t*)H;
    float2 acc = make_float2(0.f, 0.f);
    #pragma unroll 4
    for (int e = beg; e < end; ++e) {
        int s = g_col[e];
        float w = __ldg(&g_dinv[s]);
        uint32_t hv = __ldg(&Hv[(size_t)s * 32 + lane]);
        float2 h = __half22float2(*(__half2*)&hv);
        acc.x = fmaf(w, h.x, acc.x);
        acc.y = fmaf(w, h.y, acc.y);
    }
    float di = g_dinv[warp];
    float ws = di * di;
    uint32_t sv = Hv[(size_t)warp * 32 + lane];
    float2 self = __half22float2(*(__half2*)&sv);
    float2 b = ((const float2*)bias)[lane];
    float2 r;
    r.x = fmaf(di, acc.x, ws * self.x) + b.x;
    r.y = fmaf(di, acc.y, ws * self.y) + b.y;
    ((float2*)out)[(size_t)warp * 32 + lane] = r;
}

// ---------------- launch ----------------
extern "C" void kernel_launch(void* const* d_in, const int* in_sizes, int n_in,
                              void* d_out, int out_size) {
    const float* x  = (const float*)d_in[0];
    const void*  ei = d_in[1];
    const float* W1 = (const float*)d_in[2];
    const float* b1 = (const float*)d_in[3];
    const float* W2 = (const float*)d_in[4];
    const float* b2 = (const float*)d_in[5];
    float* out = (float*)d_out;

    __half *H1h, *H2h;
    float *A1;
    __half *w1h, *w2h, *w2l;
    int *degP, *flagP;
    cudaGetSymbolAddress((void**)&H1h, g_H1h);
    cudaGetSymbolAddress((void**)&H2h, g_H2h);
    cudaGetSymbolAddress((void**)&A1, g_A1);
    cudaGetSymbolAddress((void**)&w1h, g_w1h);
    cudaGetSymbolAddress((void**)&w2h, g_w2h);
    cudaGetSymbolAddress((void**)&w2l, g_w2l);
    cudaGetSymbolAddress((void**)&degP, g_deg);
    cudaGetSymbolAddress((void**)&flagP, g_bflag);

    constexpr int ST = 72;
    const int SM1 = (128 * ST + 128 * ST) * (int)sizeof(__half);            // 36864
    const int SM2 = (128 * ST + 64 * ST + 64 * ST) * (int)sizeof(__half);   // 36864
    cudaFuncSetAttribute((const void*)gemm_hmma<HID, IND, true, false>,
                         cudaFuncAttributeMaxDynamicSharedMemorySize, SM1);
    cudaFuncSetAttribute((const void*)gemm_hmma<OUTD, HID, true, true>,
                         cudaFuncAttributeMaxDynamicSharedMemorySize, SM2);

    const int TB = 256;
    const int gQ = (NE / 4 + TB - 1) / TB;
    const int gH = (NE / 2 + TB - 1) / TB;
    const int gM = (NN + 127) / 128;

    cudaStream_t s2;
    cudaEvent_t evFork, evJoin;
    cudaStreamCreateWithFlags(&s2, cudaStreamNonBlocking);
    cudaEventCreateWithFlags(&evFork, cudaEventDisableTiming);
    cudaEventCreateWithFlags(&evJoin, cudaEventDisableTiming);

    cudaEventRecord(evFork, 0);
    cudaStreamWaitEvent(s2, evFork, 0);

    // ---- side stream: edge normalization + CSR build ----
    k_detect<<<1, 32, 0, s2>>>((const int*)ei);
    cudaMemsetAsync(degP, 0, NN * sizeof(int), s2);
    cudaMemsetAsync(flagP, 0, NBLK_SCAN * sizeof(int), s2);
    k_convert_count4<<<gQ, TB, 0, s2>>>(ei);
    k_scan<<<NBLK_SCAN, 1024, 0, s2>>>();
    k_fill2<<<gH, TB, 0, s2>>>();
    cudaEventRecord(evJoin, s2);

    // ---- main stream: weight pack + layer-1 GEMM (independent of CSR) ----
    k_pack<<<(HID * IND + TB - 1) / TB, TB>>>(W1, W2);
    gemm_hmma<HID, IND, true, false><<<gM, 256, SM1>>>(x, w1h, nullptr, H1h, NN);

    // join: aggregation needs both CSR and H1
    cudaStreamWaitEvent(0, evJoin, 0);
    k_agg128h<<<(NN * 32 + TB - 1) / TB, TB>>>(H1h, b1, A1);

    // layer 2
    gemm_hmma<OUTD, HID, true, true><<<gM, 256, SM2>>>(A1, w2h, w2l, H2h, NN);
    k_agg64h<<<(NN * 32 + TB - 1) / TB, TB>>>(H2h, b2, out);
}